// round 16
// baseline (speedup 1.0000x reference)
#include <cuda_runtime.h>

#define B_ 8
#define C_ 64
#define H_ 256
#define W_ 256
#define E_ 256
#define NH_ 8
#define HD_ 32
#define NPIX (H_*W_)
#define PST 68

// smem floats: xs[16384] | la[2048] | w8[1024]  == 19456 floats = 77824 B -> occ 3
#define XS_F   (256*64)
#define LA_F   (256*8)
#define W8_F   (64*16)
#define SMEM_FLOATS (XS_F + LA_F + W8_F)

__device__ float g_wa[B_*NH_*C_];
__device__ float g_wb[B_*NH_*C_];
__device__ float g_wc[B_*NH_*C_];
__device__ float g_s [B_*NH_*3];
__device__ float g_part[(size_t)B_*H_*NH_*PST];

#define FMA2(a, x, w) asm("fma.rn.f32x2 %0, %1, %2, %0;" : "+l"(a) : "l"(x), "l"(w))

// ---------------------------------------------------------------------------
// Prep (unchanged)
// ---------------------------------------------------------------------------
__global__ void prep_kernel(const float* __restrict__ z,  const float* __restrict__ pos,
                            const float* __restrict__ Wq, const float* __restrict__ bq,
                            const float* __restrict__ Wk, const float* __restrict__ bk,
                            const float* __restrict__ Wp, const float* __restrict__ bp)
{
    int b = blockIdx.x >> 3, h = blockIdx.x & 7;
    __shared__ float tA[HD_], tB[HD_], tC[HD_];
    int tid = threadIdx.x;
    const float s = 0.1767766952966369f;  // 1/sqrt(32)

    int c2 = tid >> 2, sub = tid & 3;
    float wkr[8];
    #pragma unroll
    for (int d = 0; d < 8; d++)
        wkr[d] = __ldg(Wk + (h*HD_ + sub*8 + d)*C_ + c2);

    {
        int d = tid >> 3, q = tid & 7;
        int e = h*HD_ + d;
        const float4* zr = reinterpret_cast<const float4*>(z + b*C_);
        const float4* wq = reinterpret_cast<const float4*>(Wq + e*C_);
        float4 z0 = zr[q*2], z1 = zr[q*2+1];
        float4 w0 = __ldg(wq + q*2), w1 = __ldg(wq + q*2 + 1);
        float qv = z0.x*w0.x + z0.y*w0.y + z0.z*w0.z + z0.w*w0.w
                 + z1.x*w1.x + z1.y*w1.y + z1.z*w1.z + z1.w*w1.w;
        qv += __shfl_xor_sync(0xffffffffu, qv, 1);
        qv += __shfl_xor_sync(0xffffffffu, qv, 2);
        qv += __shfl_xor_sync(0xffffffffu, qv, 4);
        if (q == 0) {
            qv += bq[e];
            float wp0 = Wp[2*d], wp1 = Wp[2*d+1];
            float p0 = pos[(b*NH_+h)*2], p1 = pos[(b*NH_+h)*2+1];
            float cc = bp[d] - wp0*p0 - wp1*p1;
            tA[d] = qv*wp0*s; tB[d] = qv*wp1*s; tC[d] = qv*cc*s;
        }
    }
    __syncthreads();
    {
        float a = 0.f, bb = 0.f, cc = 0.f;
        #pragma unroll
        for (int d = 0; d < 8; d++) {
            int dd = sub*8 + d;
            float w = wkr[d];
            a += tA[dd]*w; bb += tB[dd]*w; cc += tC[dd]*w;
        }
        a  += __shfl_xor_sync(0xffffffffu, a, 1);
        bb += __shfl_xor_sync(0xffffffffu, bb, 1);
        cc += __shfl_xor_sync(0xffffffffu, cc, 1);
        a  += __shfl_xor_sync(0xffffffffu, a, 2);
        bb += __shfl_xor_sync(0xffffffffu, bb, 2);
        cc += __shfl_xor_sync(0xffffffffu, cc, 2);
        if (sub == 0) {
            int base = (b*NH_+h)*C_;
            g_wa[base+c2] = a; g_wb[base+c2] = bb; g_wc[base+c2] = cc;
        }
    }
    if (tid < 3) {
        const float* t = (tid==0) ? tA : ((tid==1) ? tB : tC);
        float sv = 0.f;
        #pragma unroll
        for (int d = 0; d < HD_; d++) sv += t[d]*bk[h*HD_ + d];
        g_s[(b*NH_+h)*3 + tid] = sv;
    }
}

// ---------------------------------------------------------------------------
// Main: fused staging + phase A. Thread owns pixel-quad q=tid>>1, channels
// c == (tid&1) mod 2. Logit partials accumulate in registers as x streams in;
// cross-half reduce via shfl_xor(..,1). Phase B/softmax/combine as r15.
//   xs swizzle: word(p,c) = p*64 + ((c + 2*(p>>2) + 8*(p&3)) & 63)
// ---------------------------------------------------------------------------
__global__ void __launch_bounds__(128, 3) main_kernel(const float* __restrict__ x)
{
    extern __shared__ float sm[];
    float* xs   = sm;                      // [256*64] swizzled
    float* la   = sm + XS_F;               // [256][8] attn; [0..15] = srow/sbv early
    float* w8   = la + LA_F;               // [64][16]; aliased by red then Sp
    float* srow = la;                      // [8]
    float* sbv  = la + 8;                  // [8]
    float* red_m = w8, *red_t = w8 + 32, *red_pj = w8 + 64, *mfin = w8 + 96;

    int row = blockIdx.x, b = blockIdx.y;
    int tid = threadIdx.x;
    int warp = tid >> 5, lane = tid & 31;
    int q = tid >> 1, half = tid & 1;

    const float* xg = x + (size_t)b*C_*NPIX + (size_t)row*W_;

    // ---- prologue: issue first two LDG batches (channels c = half + 2k)
    float4 va[4], vb[4];
    #pragma unroll
    for (int j = 0; j < 4; j++)
        va[j] = __ldg(reinterpret_cast<const float4*>(xg + (size_t)(half + 2*j)*NPIX) + q);
    #pragma unroll
    for (int j = 0; j < 4; j++)
        vb[j] = __ldg(reinterpret_cast<const float4*>(xg + (size_t)(half + 2*(4+j))*NPIX) + q);

    // per-row combined weights (overlaps LDG latency)
    if (tid < 64) {
        int c = tid;
        float rf = (float)row;
        #pragma unroll
        for (int h = 0; h < 8; h++) {
            int gi = (b*NH_+h)*C_ + c;
            w8[c*16 + 2*h]     = g_wc[gi] + rf*g_wa[gi];
            w8[c*16 + 2*h + 1] = g_wb[gi];
        }
    } else if (tid < 72) {
        int h = tid - 64;
        srow[h] = g_s[(b*NH_+h)*3+2] + (float)row*g_s[(b*NH_+h)*3+0];
        sbv[h]  = g_s[(b*NH_+h)*3+1];
    }
    __syncthreads();   // w8/srow ready

    // ---- fused staging + logit accumulation
    unsigned long long acc[32];
    #pragma unroll
    for (int i = 0; i < 32; i++) acc[i] = 0ULL;

    int sbase = (4*q)*64;
    int s0 = (2*q) & 63;    // col offset for i=0 (plus c)

    #pragma unroll
    for (int kb = 0; kb < 8; kb++) {
        #pragma unroll
        for (int j = 0; j < 4; j++) {
            float4 v = (kb & 1) ? vb[j] : va[j];
            int c = half + 2*(4*kb + j);
            // swizzled STS: p = 4q+i, col = (c + 2q + 8i) & 63
            xs[sbase       + ((c + s0     ) & 63)] = v.x;
            xs[sbase + 64  + ((c + s0 + 8 ) & 63)] = v.y;
            xs[sbase + 128 + ((c + s0 + 16) & 63)] = v.z;
            xs[sbase + 192 + ((c + s0 + 24) & 63)] = v.w;
            const ulonglong2* wp = reinterpret_cast<const ulonglong2*>(w8 + c*16);
            ulonglong2 wA = wp[0], wB = wp[1], wC = wp[2], wD = wp[3];
            unsigned long long xx;
            asm("mov.b64 %0, {%1, %1};" : "=l"(xx) : "f"(v.x));
            FMA2(acc[0], xx, wA.x); FMA2(acc[1], xx, wA.y);
            FMA2(acc[2], xx, wB.x); FMA2(acc[3], xx, wB.y);
            FMA2(acc[4], xx, wC.x); FMA2(acc[5], xx, wC.y);
            FMA2(acc[6], xx, wD.x); FMA2(acc[7], xx, wD.y);
            asm("mov.b64 %0, {%1, %1};" : "=l"(xx) : "f"(v.y));
            FMA2(acc[8],  xx, wA.x); FMA2(acc[9],  xx, wA.y);
            FMA2(acc[10], xx, wB.x); FMA2(acc[11], xx, wB.y);
            FMA2(acc[12], xx, wC.x); FMA2(acc[13], xx, wC.y);
            FMA2(acc[14], xx, wD.x); FMA2(acc[15], xx, wD.y);
            asm("mov.b64 %0, {%1, %1};" : "=l"(xx) : "f"(v.z));
            FMA2(acc[16], xx, wA.x); FMA2(acc[17], xx, wA.y);
            FMA2(acc[18], xx, wB.x); FMA2(acc[19], xx, wB.y);
            FMA2(acc[20], xx, wC.x); FMA2(acc[21], xx, wC.y);
            FMA2(acc[22], xx, wD.x); FMA2(acc[23], xx, wD.y);
            asm("mov.b64 %0, {%1, %1};" : "=l"(xx) : "f"(v.w));
            FMA2(acc[24], xx, wA.x); FMA2(acc[25], xx, wA.y);
            FMA2(acc[26], xx, wB.x); FMA2(acc[27], xx, wB.y);
            FMA2(acc[28], xx, wC.x); FMA2(acc[29], xx, wC.y);
            FMA2(acc[30], xx, wD.x); FMA2(acc[31], xx, wD.y);
        }
        if (kb < 6) {
            #pragma unroll
            for (int j = 0; j < 4; j++) {
                int c = half + 2*(4*(kb+2) + j);
                float4 nv = __ldg(reinterpret_cast<const float4*>(xg + (size_t)c*NPIX) + q);
                if (kb & 1) vb[j] = nv; else va[j] = nv;
            }
        }
    }
    __syncthreads();   // xs complete; all w8 reads done (red_* may alias w8)

    // ---- cross-half reduce (partner tid^1, same warp)
    float sr[32], sbb[32];
    #pragma unroll
    for (int i = 0; i < 32; i++) {
        unsigned long long o = __shfl_xor_sync(0xffffffffu, acc[i], 1);
        float r0, b0, r1, b1;
        asm("mov.b64 {%0, %1}, %2;" : "=f"(r0), "=f"(b0) : "l"(acc[i]));
        asm("mov.b64 {%0, %1}, %2;" : "=f"(r1), "=f"(b1) : "l"(o));
        sr[i] = r0 + r1; sbb[i] = b0 + b1;
    }

    // ---- logits for my 2 pixels: p0 = 2*tid, p1 = 2*tid+1
    float l0[8], l1[8];
    {
        float p0f = (float)(2*tid), p1f = (float)(2*tid + 1);
        if (half == 0) {
            #pragma unroll
            for (int h = 0; h < 8; h++) {
                l0[h] = (sr[h]     + srow[h]) + p0f*(sbb[h]     + sbv[h]);
                l1[h] = (sr[8 + h] + srow[h]) + p1f*(sbb[8 + h] + sbv[h]);
            }
        } else {
            #pragma unroll
            for (int h = 0; h < 8; h++) {
                l0[h] = (sr[16 + h] + srow[h]) + p0f*(sbb[16 + h] + sbv[h]);
                l1[h] = (sr[24 + h] + srow[h]) + p1f*(sbb[24 + h] + sbv[h]);
            }
        }
    }

    int col0 = 2*tid, col1 = 2*tid + 1;

    // ---- softmax over the row
    {
        float mh[8];
        #pragma unroll
        for (int h = 0; h < 8; h++) mh[h] = fmaxf(l0[h], l1[h]);
        #pragma unroll
        for (int o = 16; o; o >>= 1) {
            #pragma unroll
            for (int h = 0; h < 8; h++)
                mh[h] = fmaxf(mh[h], __shfl_xor_sync(0xffffffffu, mh[h], o));
        }
        if (lane == 0) {
            #pragma unroll
            for (int h = 0; h < 8; h++) red_m[warp*8 + h] = mh[h];
        }
        __syncthreads();
        if (tid < 8)
            mfin[tid] = fmaxf(fmaxf(red_m[tid], red_m[8+tid]),
                              fmaxf(red_m[16+tid], red_m[24+tid]));
        __syncthreads();

        float th[8], pjh[8], e0[8], e1[8];
        float c0f = (float)col0, c1f = (float)col1;
        #pragma unroll
        for (int h = 0; h < 8; h++) {
            float M = mfin[h];
            e0[h] = __expf(l0[h] - M);
            e1[h] = __expf(l1[h] - M);
            th[h]  = e0[h] + e1[h];
            pjh[h] = e0[h]*c0f + e1[h]*c1f;
        }
        *reinterpret_cast<float4*>(la + col0*8)     = make_float4(e0[0], e0[1], e0[2], e0[3]);
        *reinterpret_cast<float4*>(la + col0*8 + 4) = make_float4(e0[4], e0[5], e0[6], e0[7]);
        *reinterpret_cast<float4*>(la + col1*8)     = make_float4(e1[0], e1[1], e1[2], e1[3]);
        *reinterpret_cast<float4*>(la + col1*8 + 4) = make_float4(e1[4], e1[5], e1[6], e1[7]);

        #pragma unroll
        for (int o = 16; o; o >>= 1) {
            #pragma unroll
            for (int h = 0; h < 8; h++) {
                th[h]  += __shfl_xor_sync(0xffffffffu, th[h],  o);
                pjh[h] += __shfl_xor_sync(0xffffffffu, pjh[h], o);
            }
        }
        if (lane == 0) {
            #pragma unroll
            for (int h = 0; h < 8; h++) {
                red_t[warp*8 + h]  = th[h];
                red_pj[warp*8 + h] = pjh[h];
            }
        }
        __syncthreads();
        if (tid < 8) {
            float T  = red_t[tid]  + red_t[8+tid]  + red_t[16+tid]  + red_t[24+tid];
            float PJ = red_pj[tid] + red_pj[8+tid] + red_pj[16+tid] + red_pj[24+tid];
            size_t pb = ((size_t)(b*H_ + row)*NH_ + tid)*PST;
            g_part[pb + 64] = mfin[tid];
            g_part[pb + 65] = T;
            g_part[pb + 66] = PJ;
        }
    }

    // ---- Phase B: S[h][c] = sum_p e[p][h]*x[p][c], head-pairs via FMA2
    {
        int c = tid & 63, g = tid >> 6;
        unsigned long long bacc[4];
        #pragma unroll
        for (int j = 0; j < 4; j++) bacc[j] = 0ULL;
        int pbase = g*128;
        #pragma unroll 4
        for (int i = 0; i < 128; i++) {
            int p = pbase + i;
            int col = (c + ((p & 3) << 3) + 2*(p >> 2)) & 63;
            float xv = xs[p*64 + col];
            unsigned long long xx;
            asm("mov.b64 %0, {%1, %1};" : "=l"(xx) : "f"(xv));
            ulonglong2 eA = *reinterpret_cast<const ulonglong2*>(la + p*8);
            ulonglong2 eB = *reinterpret_cast<const ulonglong2*>(la + p*8 + 4);
            FMA2(bacc[0], xx, eA.x);
            FMA2(bacc[1], xx, eA.y);
            FMA2(bacc[2], xx, eB.x);
            FMA2(bacc[3], xx, eB.y);
        }
        float* Sp = w8;  // reuse
        __syncthreads();
        *reinterpret_cast<ulonglong2*>(Sp + tid*8)     = make_ulonglong2(bacc[0], bacc[1]);
        *reinterpret_cast<ulonglong2*>(Sp + tid*8 + 4) = make_ulonglong2(bacc[2], bacc[3]);
        __syncthreads();
        if (tid < 64) {
            size_t chk = (size_t)(b*H_ + row)*NH_;
            #pragma unroll
            for (int h = 0; h < 8; h++)
                g_part[(chk + h)*PST + tid] = Sp[tid*8 + h] + Sp[(tid+64)*8 + h];
        }
    }
}

// ---------------------------------------------------------------------------
// Combine (unchanged)
// ---------------------------------------------------------------------------
__global__ void combine_kernel(const float* __restrict__ Wv, const float* __restrict__ bv,
                               float* __restrict__ out)
{
    int b = blockIdx.x >> 3, h = blockIdx.x & 7;
    __shared__ float fsh[256], Ssh[64], Sp[4][64];
    __shared__ float wred[8], wsum[8][3];
    __shared__ float Msh;
    int tid = threadIdx.x, warp = tid >> 5, lane = tid & 31;

    const float* pb = g_part + ((size_t)(b*H_+tid)*NH_ + h)*PST;
    float m = pb[64], T0 = pb[65], PJ0 = pb[66];

    float mm = m;
    #pragma unroll
    for (int o = 16; o; o >>= 1) mm = fmaxf(mm, __shfl_xor_sync(0xffffffffu, mm, o));
    if (lane == 0) wred[warp] = mm;
    __syncthreads();
    if (tid == 0) {
        float M = wred[0];
        #pragma unroll
        for (int i = 1; i < 8; i++) M = fmaxf(M, wred[i]);
        Msh = M;
    }
    __syncthreads();
    float M = Msh;
    float f = __expf(m - M);
    fsh[tid] = f;
    float Tl = T0*f, P0 = Tl*(float)tid, P1 = PJ0*f;
    #pragma unroll
    for (int o = 16; o; o >>= 1) {
        Tl += __shfl_xor_sync(0xffffffffu, Tl, o);
        P0 += __shfl_xor_sync(0xffffffffu, P0, o);
        P1 += __shfl_xor_sync(0xffffffffu, P1, o);
    }
    if (lane == 0) { wsum[warp][0] = Tl; wsum[warp][1] = P0; wsum[warp][2] = P1; }
    __syncthreads();
    float Tsh = 0.f, P0sh = 0.f, P1sh = 0.f;
    #pragma unroll
    for (int i = 0; i < 8; i++) { Tsh += wsum[i][0]; P0sh += wsum[i][1]; P1sh += wsum[i][2]; }

    int c = tid & 63, seg = tid >> 6;
    float sacc = 0.f;
    const float* pbase = g_part + ((size_t)(b*H_ + seg*64)*NH_ + h)*PST + c;
    #pragma unroll 4
    for (int i = 0; i < 64; i++)
        sacc += pbase[(size_t)i*NH_*PST] * fsh[seg*64 + i];
    Sp[seg][c] = sacc; __syncthreads();
    if (tid < 64) Ssh[tid] = (Sp[0][tid] + Sp[1][tid] + Sp[2][tid] + Sp[3][tid]) / Tsh;
    __syncthreads();

    int e = tid;
    float acc = bv[e];
    const float4* wv = reinterpret_cast<const float4*>(Wv + e*C_);
    const float4* ss = reinterpret_cast<const float4*>(Ssh);
    #pragma unroll
    for (int c2 = 0; c2 < 16; c2++) {
        float4 w = __ldg(wv + c2), sv = ss[c2];
        acc += w.x*sv.x + w.y*sv.y + w.z*sv.z + w.w*sv.w;
    }
    out[(size_t)(b*NH_+h)*E_ + e] = acc;

    if (tid == 0) {
        float invT = 1.f/Tsh;
        out[B_*NH_*E_ + (b*NH_+h)*2]     = P0sh*invT;
        out[B_*NH_*E_ + (b*NH_+h)*2 + 1] = P1sh*invT;
    }
}

extern "C" void kernel_launch(void* const* d_in, const int* in_sizes, int n_in,
                              void* d_out, int out_size)
{
    const float* x   = (const float*)d_in[0];
    const float* z   = (const float*)d_in[1];
    const float* pos = (const float*)d_in[2];
    const float* Wq  = (const float*)d_in[3];
    const float* bq  = (const float*)d_in[4];
    const float* Wk  = (const float*)d_in[5];
    const float* bk  = (const float*)d_in[6];
    const float* Wv  = (const float*)d_in[7];
    const float* bv  = (const float*)d_in[8];
    const float* Wp  = (const float*)d_in[9];
    const float* bp  = (const float*)d_in[10];
    float* out = (float*)d_out;

    cudaFuncSetAttribute(main_kernel, cudaFuncAttributeMaxDynamicSharedMemorySize,
                         SMEM_FLOATS * (int)sizeof(float));

    prep_kernel<<<B_*NH_, 256>>>(z, pos, Wq, bq, Wk, bk, Wp, bp);
    main_kernel<<<dim3(H_, B_), 128, SMEM_FLOATS * sizeof(float)>>>(x);
    combine_kernel<<<B_*NH_, 256>>>(Wv, bv, out);
}